// round 1
// baseline (speedup 1.0000x reference)
#include <cuda_runtime.h>

// out = 0.9*p + 0.1 * softmax(-4 p p^T) @ p     (N=16384, D=64, fp32)
// Flash-attention formulation, SIMT fp32 with packed f32x2 FMA.

#define DDIM     64
#define NROWS    64      // query rows per block
#define SPLIT    4       // key-range split per row
#define NTHREADS 256     // NROWS * SPLIT
#define TK       64      // keys per smem tile

typedef unsigned long long u64;

__device__ __forceinline__ u64 pack2(float x, float y) {
    u64 r; asm("mov.b64 %0, {%1, %2};" : "=l"(r) : "f"(x), "f"(y)); return r;
}
__device__ __forceinline__ void unpack2(u64 v, float &x, float &y) {
    asm("mov.b64 {%0, %1}, %2;" : "=f"(x), "=f"(y) : "l"(v));
}
__device__ __forceinline__ void fma2(u64 &d, u64 a, u64 b) {
    asm("fma.rn.f32x2 %0, %1, %2, %0;" : "+l"(d) : "l"(a), "l"(b));
}
__device__ __forceinline__ void mul2(u64 &d, u64 a) {
    asm("mul.rn.f32x2 %0, %0, %1;" : "+l"(d) : "l"(a));
}
__device__ __forceinline__ u64 add2(u64 a, u64 b) {
    u64 r; asm("add.rn.f32x2 %0, %1, %2;" : "=l"(r) : "l"(a), "l"(b)); return r;
}

__global__ __launch_bounds__(NTHREADS, 1)
void gradattn_kernel(const float* __restrict__ p, float* __restrict__ out, int N) {
    // Double-buffered K tile: 2 x 64 keys x 64 floats = 32 KB (as 16B vectors).
    __shared__ ulonglong2 kt[2][TK][16];
    __shared__ float mbuf[SPLIT][NROWS];
    __shared__ float lbuf[SPLIT][NROWS];
    __shared__ float Lbuf[NROWS];

    const int tid  = threadIdx.x;
    const int s    = tid >> 6;          // key subgroup 0..3 (warp-uniform)
    const int r    = tid & 63;          // row within block
    const int grow = blockIdx.x * NROWS + r;

    // Load this thread's query row into registers, packed as f32x2.
    u64 q2[32];
    {
        const u64* qp = (const u64*)(p + (size_t)grow * DDIM);
        #pragma unroll
        for (int i = 0; i < 32; i++) q2[i] = qp[i];
    }

    u64 acc2[32];
    #pragma unroll
    for (int i = 0; i < 32; i++) acc2[i] = 0ULL;   // bits of (0.0f, 0.0f)
    float m = -1e30f;
    float l = 0.0f;

    const ulonglong2* pg = (const ulonglong2*)p;   // 16B-vector view of p
    const int NT = N / TK;

    // Preload tile 0 (coalesced: 256 threads x 4 x 16B).
    {
        ulonglong2* dst = (ulonglong2*)kt[0];
        #pragma unroll
        for (int u = 0; u < 4; u++)
            dst[tid + u * NTHREADS] = pg[tid + u * NTHREADS];
    }
    __syncthreads();

    for (int t = 0; t < NT; t++) {
        const int cur = t & 1;
        const bool hasnext = (t + 1 < NT);
        ulonglong2 pf0, pf1, pf2, pf3;
        if (hasnext) {
            const ulonglong2* src = pg + (size_t)(t + 1) * (TK * 16);
            pf0 = src[tid];
            pf1 = src[tid + 256];
            pf2 = src[tid + 512];
            pf3 = src[tid + 768];
        }

        const ulonglong2 (*kb)[16] = kt[cur];

        // ---- scores for this thread's 16 keys of the tile ----
        float tv[16];
        #pragma unroll
        for (int kk = 0; kk < 16; kk++) {
            const ulonglong2* krow = kb[s * 16 + kk];   // broadcast within warp
            u64 da = 0ULL, db = 0ULL;
            #pragma unroll
            for (int i = 0; i < 16; i += 2) {
                ulonglong2 kv0 = krow[i];
                ulonglong2 kv1 = krow[i + 1];
                fma2(da, q2[2 * i],     kv0.x);
                fma2(db, q2[2 * i + 1], kv0.y);
                fma2(da, q2[2 * i + 2], kv1.x);
                fma2(db, q2[2 * i + 3], kv1.y);
            }
            u64 dsum = add2(da, db);
            float x, y; unpack2(dsum, x, y);
            tv[kk] = -4.0f * (x + y);                   // logit = -scores
        }

        // ---- online softmax: chunk max, rare rescale ----
        float mc = tv[0];
        #pragma unroll
        for (int kk = 1; kk < 16; kk++) mc = fmaxf(mc, tv[kk]);
        if (mc > m) {
            float sc = __expf(m - mc);
            m = mc;
            l *= sc;
            u64 sc2 = pack2(sc, sc);
            #pragma unroll
            for (int i = 0; i < 32; i++) mul2(acc2[i], sc2);
        }

        // ---- accumulate weighted values ----
        #pragma unroll
        for (int kk = 0; kk < 16; kk++) {
            float w = __expf(tv[kk] - m);
            l += w;
            u64 w2 = pack2(w, w);
            const ulonglong2* krow = kb[s * 16 + kk];
            #pragma unroll
            for (int i = 0; i < 16; i++) {
                ulonglong2 kv = krow[i];
                fma2(acc2[2 * i],     w2, kv.x);
                fma2(acc2[2 * i + 1], w2, kv.y);
            }
        }

        // ---- stage next tile (writes other buffer; safe vs. current reads) ----
        if (hasnext) {
            ulonglong2* dst = (ulonglong2*)kt[cur ^ 1];
            dst[tid]       = pf0;
            dst[tid + 256] = pf1;
            dst[tid + 512] = pf2;
            dst[tid + 768] = pf3;
        }
        __syncthreads();
    }

    // ---- merge the 4 key-split softmax states per row ----
    mbuf[s][r] = m;
    lbuf[s][r] = l;
    __syncthreads();

    const float M = fmaxf(fmaxf(mbuf[0][r], mbuf[1][r]),
                          fmaxf(mbuf[2][r], mbuf[3][r]));
    const float f = __expf(m - M);
    lbuf[s][r] = l * f;               // rescaled partial denominators

    // Overlay merge buffer on the (now dead) K tiles; stride 65 avoids conflicts.
    float* ab = (float*)kt;
    #pragma unroll 1
    for (int sx = 0; sx < SPLIT; sx++) {
        if (s == sx) {
            float* dst = ab + r * 65;
            #pragma unroll
            for (int i = 0; i < 32; i++) {
                float x, y; unpack2(acc2[i], x, y);
                if (sx == 0) { dst[2 * i] = f * x;  dst[2 * i + 1] = f * y; }
                else         { dst[2 * i] += f * x; dst[2 * i + 1] += f * y; }
            }
        }
        __syncthreads();
    }

    if (s == 0)
        Lbuf[r] = lbuf[0][r] + lbuf[1][r] + lbuf[2][r] + lbuf[3][r];
    __syncthreads();

    // ---- epilogue: out = p + 0.1 * (acc/L - p) ----
    const float* pb = p   + (size_t)blockIdx.x * NROWS * DDIM;
    float*       ob = out + (size_t)blockIdx.x * NROWS * DDIM;
    for (int i = tid; i < NROWS * DDIM; i += NTHREADS) {
        int rr = i >> 6, dd = i & 63;
        float pv = pb[i];
        float av = ab[rr * 65 + dd] / Lbuf[rr];
        ob[i] = fmaf(0.1f, av - pv, pv);
    }
}

extern "C" void kernel_launch(void* const* d_in, const int* in_sizes, int n_in,
                              void* d_out, int out_size) {
    const float* p = (const float*)d_in[0];
    float* out = (float*)d_out;
    const int N = in_sizes[0] / DDIM;        // 16384
    gradattn_kernel<<<N / NROWS, NTHREADS>>>(p, out, N);
}